// round 8
// baseline (speedup 1.0000x reference)
#include <cuda_runtime.h>
#include <cuda_fp16.h>
#include <math.h>

#define HC 64
#define NF 64
#define NG 5
#define SL 20
#define ZD 148
#define BN_EPS 1e-5f
#define MAX_N 50000
#define MAX_E 800000

typedef unsigned long long ull;

// Scratch (allocation-free rule: __device__ globals)
__device__ __align__(16) float    g_agg[MAX_N * NF];
__device__ __align__(16) float    g_projA[MAX_N * 128];     // fp32 [N][Af|As] (biases incl.)
__device__ __align__(16) uint2    g_projB[MAX_N * 32];      // fp16 [N][lane]=(f2,s2) of Bf|Bs
__device__ __align__(16) float    g_ea[(size_t)MAX_E * SL]; // relu(edge_attr@short_w), edge order
__device__ __align__(16) unsigned g_epf[(size_t)MAX_E * 32]; // fp16x2 f-part, BUCKET order
__device__ __align__(16) unsigned g_eps[(size_t)MAX_E * 32]; // fp16x2 s-part, BUCKET order
__device__ __align__(16) float    g_sums[2 * NF];
__device__ int  g_deg[MAX_N];
__device__ int  g_off[MAX_N];
__device__ int  g_cur[MAX_N];
__device__ int  g_pos[MAX_E];                               // edge id -> bucket pos
__device__ __align__(8) int2 g_es[MAX_E];                   // bucket order: (src, edge_id)

// ---------------- packed helpers ----------------
__device__ __forceinline__ ull fma2(ull a, ull b, ull c) {
    ull d;
    asm("fma.rn.f32x2 %0, %1, %2, %3;" : "=l"(d) : "l"(a), "l"(b), "l"(c));
    return d;
}
__device__ __forceinline__ ull pack2(float v) {
    ull r;
    asm("mov.b64 %0, {%1, %1};" : "=l"(r) : "f"(v));
    return r;
}
__device__ __forceinline__ float2 unpack2(ull v) {
    float2 r;
    asm("mov.b64 {%0, %1}, %2;" : "=f"(r.x), "=f"(r.y) : "l"(v));
    return r;
}
__device__ __forceinline__ float sigmoid_t(float x) {
    float t;
    asm("tanh.approx.f32 %0, %1;" : "=f"(t) : "f"(0.5f * x));
    return fmaf(0.5f, t, 0.5f);
}
__device__ __forceinline__ float msg_fn(float f, float s) {
    float sp = fmaxf(s, 0.f) + __logf(1.f + __expf(-fabsf(s)));
    return sigmoid_t(f) * sp;
}

// ---------------------------------------------------------------------------
// Launch 1: fused [zero_deg | lin0 | ea]
#define K1_ZB 64
#define K1_LB 592
#define K1_EB 1184
#define K1_GRID (K1_ZB + K1_LB + K1_EB)

__global__ __launch_bounds__(256) void fused_pre_kernel(
    const float* __restrict__ h, const float* __restrict__ lw,
    const float* __restrict__ lb, float* __restrict__ out,
    const float* __restrict__ attr, const float* __restrict__ sw,
    const float* __restrict__ sb, int N, int E)
{
    __shared__ float smem[64 * 64 + 64];
    int tid = threadIdx.x;
    int b = blockIdx.x;

    if (b < K1_ZB) {
        int stride = K1_ZB * 256;
        for (int i = b * 256 + tid; i < N; i += stride) g_deg[i] = 0;
        return;
    }
    b -= K1_ZB;
    if (b < K1_LB) {
        float* sW = smem;
        float* sbv = smem + 64 * 64;
        for (int i = tid; i < 64 * 64; i += 256) sW[i] = lw[i];
        if (tid < 64) sbv[tid] = lb[tid];
        __syncthreads();
        int c = tid & 63, rr = tid >> 6;
        for (int r0 = b * 4; r0 < N; r0 += K1_LB * 4) {
            int r = r0 + rr;
            if (r < N) {
                const float* hr = h + (size_t)r * 64;
                float acc = sbv[c];
#pragma unroll 16
                for (int k = 0; k < 64; k++)
                    acc = fmaf(__ldg(hr + k), sW[k * 64 + c], acc);
                out[(size_t)r * 64 + c] = fmaxf(acc, 0.f);
            }
        }
        return;
    }
    b -= K1_LB;
    {
        float* w = smem;
        float* bb = smem + NG * SL;
        if (tid < NG * SL) w[tid] = sw[tid];
        if (tid < SL)      bb[tid] = sb[tid];
        __syncthreads();
        int stride = K1_EB * 256;
        for (int e = b * 256 + tid; e < E; e += stride) {
            float a[NG];
#pragma unroll
            for (int g = 0; g < NG; g++) a[g] = __ldg(attr + (size_t)e * NG + g);
            float4* dst = (float4*)(g_ea + (size_t)e * SL);
#pragma unroll
            for (int q = 0; q < 5; q++) {
                float o[4];
#pragma unroll
                for (int j = 0; j < 4; j++) {
                    float acc = bb[q * 4 + j];
#pragma unroll
                    for (int g = 0; g < NG; g++)
                        acc = fmaf(a[g], w[g * SL + q * 4 + j], acc);
                    o[j] = fmaxf(acc, 0.f);
                }
                dst[q] = make_float4(o[0], o[1], o[2], o[3]);
            }
        }
    }
}

// ---------------------------------------------------------------------------
__global__ __launch_bounds__(256) void hist_kernel(const int* __restrict__ ei, int E) {
    int stride = gridDim.x * blockDim.x;
    for (int e = blockIdx.x * blockDim.x + threadIdx.x; e < E; e += stride)
        atomicAdd(&g_deg[__ldg(ei + E + e)], 1);
}

__global__ __launch_bounds__(1024) void scan_kernel(int N) {
    __shared__ int part[1024];
    int t = threadIdx.x;
    int C = (N + 1023) >> 10;
    int lo = t * C, hi = min(lo + C, N);
    int s = 0;
    for (int i = lo; i < hi; i++) s += g_deg[i];
    part[t] = s;
    __syncthreads();
    for (int d = 1; d < 1024; d <<= 1) {
        int v = (t >= d) ? part[t - d] : 0;
        __syncthreads();
        part[t] += v;
        __syncthreads();
    }
    int run = part[t] - s;
    for (int i = lo; i < hi; i++) {
        int d = g_deg[i];
        g_off[i] = run;
        g_cur[i] = run;
        run += d;
    }
}

__global__ __launch_bounds__(256) void scatter_kernel(const int* __restrict__ ei, int E) {
    int stride = gridDim.x * blockDim.x;
    for (int e = blockIdx.x * blockDim.x + threadIdx.x; e < E; e += stride) {
        int dst = __ldg(ei + E + e);
        int pos = atomicAdd(&g_cur[dst], 1);
        g_pos[e] = pos;
        g_es[pos] = make_int2(__ldg(ei + e), e);
    }
}

// ---------------------------------------------------------------------------
// node_proj: g_projA[n] = out[n]@[W1f|W1s]+bias (fp32);
//            g_projB[n] = fp16(out[n]@[W2f|W2s]), pair-interleaved.
// Block 0 zeroes g_sums for the layer.
__global__ __launch_bounds__(256) void node_proj_kernel(
    const float* __restrict__ out,
    const float* __restrict__ Wf, const float* __restrict__ bf,
    const float* __restrict__ Ws, const float* __restrict__ bs,
    int N)
{
    int tid = threadIdx.x;
    if (blockIdx.x == 0 && tid < 2 * NF) g_sums[tid] = 0.f;

    __shared__ __align__(16) float sOut[16 * 64];
    int c = tid;
    const float* base; int col; float bias; int isA, seg;
    if (c < 64)       { base = Wf;           col = c;       bias = __ldg(bf + c);      isA = 1; seg = 0; }
    else if (c < 128) { base = Ws;           col = c - 64;  bias = __ldg(bs + c - 64); isA = 1; seg = 1; }
    else if (c < 192) { base = Wf + 64 * 64; col = c - 128; bias = 0.f;                isA = 0; seg = 0; }
    else              { base = Ws + 64 * 64; col = c - 192; bias = 0.f;                isA = 0; seg = 1; }
    float w[64];
#pragma unroll
    for (int k = 0; k < 64; k++) w[k] = __ldg(base + k * 64 + col);
    int hidx = 4 * (col >> 1) + (col & 1) + (seg ? 2 : 0);

    for (int r0 = blockIdx.x * 16; r0 < N; r0 += gridDim.x * 16) {
        __syncthreads();
        for (int i = tid; i < 16 * 16; i += 256) {
            int r = i >> 4, q = i & 15;
            int rr = r0 + r;
            float4 v = (rr < N) ? ((const float4*)out)[(size_t)rr * 16 + q]
                                : make_float4(0.f, 0.f, 0.f, 0.f);
            ((float4*)sOut)[r * 16 + q] = v;
        }
        __syncthreads();
        float acc[16];
#pragma unroll
        for (int r = 0; r < 16; r++) acc[r] = bias;
#pragma unroll
        for (int k4 = 0; k4 < 16; k4++) {
#pragma unroll
            for (int r = 0; r < 16; r++) {
                float4 z = ((const float4*)sOut)[r * 16 + k4];
                acc[r] = fmaf(z.x, w[k4 * 4 + 0], acc[r]);
                acc[r] = fmaf(z.y, w[k4 * 4 + 1], acc[r]);
                acc[r] = fmaf(z.z, w[k4 * 4 + 2], acc[r]);
                acc[r] = fmaf(z.w, w[k4 * 4 + 3], acc[r]);
            }
        }
#pragma unroll
        for (int r = 0; r < 16; r++) {
            int rr = r0 + r;
            if (rr < N) {
                if (isA) g_projA[(size_t)rr * 128 + seg * 64 + col] = acc[r];
                else ((__half*)g_projB)[(size_t)rr * 128 + hidx] = __float2half(acc[r]);
            }
        }
    }
}

// ---------------------------------------------------------------------------
// eproj: even warps compute f = ea@W3f, odd warps s = ea@W3s (40 weight regs each).
// Reads ea sequentially (edge order); writes fp16 rows in BUCKET order (g_pos):
// scattered but full 128B-sector stores. Warp-pair processes 2 edges/iter.
__global__ __launch_bounds__(128) void eproj_kernel(
    const float* __restrict__ W3f, const float* __restrict__ W3s, int E)
{
    int lane = threadIdx.x & 31;
    int gwarp = (blockIdx.x * 128 + threadIdx.x) >> 5;
    int is_s = gwarp & 1;
    int c2 = lane * 2;

    const float* W = is_s ? W3s : W3f;
    unsigned* op = is_s ? g_eps : g_epf;

    ull w[SL];
#pragma unroll
    for (int k = 0; k < SL; k++)
        w[k] = __ldg((const ull*)(W + k * 64 + c2));

    long pw  = gwarp >> 1;                        // warp-pair index
    long npw = ((long)gridDim.x * 128 >> 5) >> 1; // number of warp pairs
    long npairs = ((long)E + 1) >> 1;

    for (long p = pw; p < npairs; p += npw) {
        long e0 = 2 * p, e1 = e0 + 1;
        bool v1 = (e1 < E);
        long e1c = v1 ? e1 : e0;
        const float4* ea0 = (const float4*)(g_ea + e0  * SL);
        const float4* ea1 = (const float4*)(g_ea + e1c * SL);
        ull f0 = 0, f1 = 0;
#pragma unroll
        for (int kk = 0; kk < 5; kk++) {
            float4 A0 = __ldg(ea0 + kk);
            float4 A1 = __ldg(ea1 + kk);
            float a0v[4] = {A0.x, A0.y, A0.z, A0.w};
            float a1v[4] = {A1.x, A1.y, A1.z, A1.w};
#pragma unroll
            for (int j = 0; j < 4; j++) {
                int k = kk * 4 + j;
                f0 = fma2(pack2(a0v[j]), w[k], f0);
                f1 = fma2(pack2(a1v[j]), w[k], f1);
            }
        }
        float2 F0 = unpack2(f0);
        __half2 h0 = __floats2half2_rn(F0.x, F0.y);
        long pos0 = __ldg(&g_pos[e0]);
        op[pos0 * 32 + lane] = *(unsigned*)&h0;
        if (v1) {
            float2 F1 = unpack2(f1);
            __half2 h1 = __floats2half2_rn(F1.x, F1.y);
            long pos1 = __ldg(&g_pos[e1]);
            op[pos1 * 32 + lane] = *(unsigned*)&h1;
        }
    }
}

// ---------------------------------------------------------------------------
// edge_agg: one warp per node. Sequential ep reads, random projB row gather.
// Fused BN stats.
__global__ __launch_bounds__(256) void edge_agg_kernel(int N)
{
    int lane = threadIdx.x & 31;
    int c2 = lane * 2;

    int warp  = (blockIdx.x * 256 + threadIdx.x) >> 5;
    int nwarp = gridDim.x * 8;

    float sx = 0.f, sy = 0.f, qx = 0.f, qy = 0.f;
    const float2* pA = (const float2*)g_projA;

    for (int n = warp; n < N; n += nwarp) {
        int beg = __ldg(&g_off[n]);
        int end = beg + __ldg(&g_deg[n]);

        float2 af = __ldg(pA + (size_t)n * 64 + lane);
        float2 as_ = __ldg(pA + (size_t)n * 64 + 32 + lane);

        float accx = 0.f, accy = 0.f;
        int i = beg;
        for (; i + 1 < end; i += 2) {
            int src0 = __ldg(&g_es[i]).x;
            int src1 = __ldg(&g_es[i + 1]).x;
            uint2 b0 = __ldg(&g_projB[(size_t)src0 * 32 + lane]);
            uint2 b1 = __ldg(&g_projB[(size_t)src1 * 32 + lane]);
            unsigned pf0 = __ldg(&g_epf[(size_t)i * 32 + lane]);
            unsigned ps0 = __ldg(&g_eps[(size_t)i * 32 + lane]);
            unsigned pf1 = __ldg(&g_epf[(size_t)(i + 1) * 32 + lane]);
            unsigned ps1 = __ldg(&g_eps[(size_t)(i + 1) * 32 + lane]);

            __half2 hf0 = __hadd2(*(__half2*)&b0.x, *(__half2*)&pf0);
            __half2 hs0 = __hadd2(*(__half2*)&b0.y, *(__half2*)&ps0);
            __half2 hf1 = __hadd2(*(__half2*)&b1.x, *(__half2*)&pf1);
            __half2 hs1 = __hadd2(*(__half2*)&b1.y, *(__half2*)&ps1);
            float2 ff0 = __half22float2(hf0), ss0 = __half22float2(hs0);
            float2 ff1 = __half22float2(hf1), ss1 = __half22float2(hs1);

            accx += msg_fn(af.x + ff0.x, as_.x + ss0.x);
            accy += msg_fn(af.y + ff0.y, as_.y + ss0.y);
            accx += msg_fn(af.x + ff1.x, as_.x + ss1.x);
            accy += msg_fn(af.y + ff1.y, as_.y + ss1.y);
        }
        if (i < end) {
            int src0 = __ldg(&g_es[i]).x;
            uint2 b0 = __ldg(&g_projB[(size_t)src0 * 32 + lane]);
            unsigned pf0 = __ldg(&g_epf[(size_t)i * 32 + lane]);
            unsigned ps0 = __ldg(&g_eps[(size_t)i * 32 + lane]);
            __half2 hf0 = __hadd2(*(__half2*)&b0.x, *(__half2*)&pf0);
            __half2 hs0 = __hadd2(*(__half2*)&b0.y, *(__half2*)&ps0);
            float2 ff0 = __half22float2(hf0), ss0 = __half22float2(hs0);
            accx += msg_fn(af.x + ff0.x, as_.x + ss0.x);
            accy += msg_fn(af.y + ff0.y, as_.y + ss0.y);
        }

        *(float2*)&g_agg[(size_t)n * 64 + c2] = make_float2(accx, accy);
        sx += accx; sy += accy;
        qx = fmaf(accx, accx, qx);
        qy = fmaf(accy, accy, qy);
    }

    atomicAdd(&g_sums[c2],          sx);
    atomicAdd(&g_sums[c2 + 1],      sy);
    atomicAdd(&g_sums[64 + c2],     qx);
    atomicAdd(&g_sums[64 + c2 + 1], qy);
}

// ---------------------------------------------------------------------------
// out = out + relu( BN(agg) + out )
__global__ __launch_bounds__(256) void bn_apply_kernel(
    const float* __restrict__ gamma, const float* __restrict__ beta,
    float* __restrict__ out, int N, float invN)
{
    int tid = threadIdx.x;
    int c0 = (tid & 15) * 4;
    float mul[4], add[4];
#pragma unroll
    for (int j = 0; j < 4; j++) {
        float mean = g_sums[c0 + j] * invN;
        float var  = fmaf(-mean, mean, g_sums[64 + c0 + j] * invN);
        float inv  = rsqrtf(var + BN_EPS);
        float m = inv * __ldg(gamma + c0 + j);
        mul[j] = m;
        add[j] = __ldg(beta + c0 + j) - mean * m;
    }
    float4* o4 = (float4*)out;
    const float4* a4 = (const float4*)g_agg;
    int total = N * 16;
    int stride = gridDim.x * 256;
    for (int i = blockIdx.x * 256 + tid; i < total; i += stride) {
        float4 a = a4[i], o = o4[i], r;
        float bn;
        bn = fmaf(a.x, mul[0], add[0]); r.x = o.x + fmaxf(bn + o.x, 0.f);
        bn = fmaf(a.y, mul[1], add[1]); r.y = o.y + fmaxf(bn + o.y, 0.f);
        bn = fmaf(a.z, mul[2], add[2]); r.z = o.z + fmaxf(bn + o.z, 0.f);
        bn = fmaf(a.w, mul[3], add[3]); r.w = o.w + fmaxf(bn + o.w, 0.f);
        o4[i] = r;
    }
}

// ---------------------------------------------------------------------------
extern "C" void kernel_launch(void* const* d_in, const int* in_sizes, int n_in,
                              void* d_out, int out_size)
{
    const float* h      = (const float*)d_in[0];
    const int*   ei     = (const int*)  d_in[1];
    // d_in[2] = edge_weight (unused by reference)
    const float* eattr  = (const float*)d_in[3];
    const float* lin0_w = (const float*)d_in[4];
    const float* lin0_b = (const float*)d_in[5];
    const float* shw    = (const float*)d_in[6];
    const float* shb    = (const float*)d_in[7];
    const float* linf_w = (const float*)d_in[8];
    const float* linf_b = (const float*)d_in[9];
    const float* lins_w = (const float*)d_in[10];
    const float* lins_b = (const float*)d_in[11];
    const float* gamma  = (const float*)d_in[12];
    const float* beta   = (const float*)d_in[13];

    int N = in_sizes[0] / HC;
    int E = in_sizes[1] / 2;
    float* out = (float*)d_out;

    const float* Wf0 = linf_w;
    const float* Ws0 = lins_w;
    const float* Wf1 = linf_w + (size_t)ZD * NF;
    const float* Ws1 = lins_w + (size_t)ZD * NF;
    float invN = 1.f / (float)N;

    // 1-3: preprocessing
    fused_pre_kernel<<<K1_GRID, 256>>>(h, lin0_w, lin0_b, out, eattr, shw, shb, N, E);
    hist_kernel<<<1480, 256>>>(ei, E);
    scan_kernel<<<1, 1024>>>(N);

    // ---- layer 0 (node_proj at slot 4 for ncu capture) ----
    node_proj_kernel<<<592, 256>>>(out, Wf0, linf_b, Ws0, lins_b, N);   // 4
    scatter_kernel<<<1480, 256>>>(ei, E);                                // 5
    eproj_kernel<<<1776, 128>>>(Wf0 + 128 * NF, Ws0 + 128 * NF, E);      // 6
    edge_agg_kernel<<<1480, 256>>>(N);                                   // 7
    bn_apply_kernel<<<592, 256>>>(gamma, beta, out, N, invN);            // 8

    // ---- layer 1 ----
    node_proj_kernel<<<592, 256>>>(out, Wf1, linf_b + NF, Ws1, lins_b + NF, N); // 9
    eproj_kernel<<<1776, 128>>>(Wf1 + 128 * NF, Ws1 + 128 * NF, E);             // 10
    edge_agg_kernel<<<1480, 256>>>(N);                                          // 11
    bn_apply_kernel<<<592, 256>>>(gamma + NF, beta + NF, out, N, invN);         // 12
}

// round 9
// speedup vs baseline: 1.8329x; 1.8329x over previous
#include <cuda_runtime.h>
#include <math.h>

#define HC 64
#define NF 64
#define NG 5
#define SL 20
#define ZD 148
#define BN_EPS 1e-5f
#define MAX_N 50000
#define MAX_E 800000

typedef unsigned long long ull;

// Scratch (allocation-free rule: __device__ globals)
__device__ __align__(16) float g_agg[MAX_N * NF];        // per-layer aggregation
__device__ __align__(16) float g_proj[MAX_N * 4 * NF];   // [N][Af|Bf|As|Bs] fp32
__device__ __align__(16) float g_ea[(size_t)MAX_E * SL]; // relu(edge_attr@short_w)
__device__ __align__(16) float g_sums[2 * NF];           // sum / sumsq

// ---------------- packed f32x2 helpers ----------------
__device__ __forceinline__ ull fma2(ull a, ull b, ull c) {
    ull d;
    asm("fma.rn.f32x2 %0, %1, %2, %3;" : "=l"(d) : "l"(a), "l"(b), "l"(c));
    return d;
}
__device__ __forceinline__ ull add2(ull a, ull b) {
    ull d;
    asm("add.rn.f32x2 %0, %1, %2;" : "=l"(d) : "l"(a), "l"(b));
    return d;
}
__device__ __forceinline__ ull pack2(float v) {
    ull r;
    asm("mov.b64 %0, {%1, %1};" : "=l"(r) : "f"(v));
    return r;
}
__device__ __forceinline__ float2 unpack2(ull v) {
    float2 r;
    asm("mov.b64 {%0, %1}, %2;" : "=f"(r.x), "=f"(r.y) : "l"(v));
    return r;
}
__device__ __forceinline__ void red_add_v4(float* addr, float a, float b, float c, float d) {
    asm volatile("red.global.add.v4.f32 [%0], {%1, %2, %3, %4};"
                 :: "l"(addr), "f"(a), "f"(b), "f"(c), "f"(d) : "memory");
}
__device__ __forceinline__ float sigmoid_t(float x) {
    float t;
    asm("tanh.approx.f32 %0, %1;" : "=f"(t) : "f"(0.5f * x));
    return fmaf(0.5f, t, 0.5f);
}
__device__ __forceinline__ float msg_fn(float f, float s) {
    float sp = fmaxf(s, 0.f) + __logf(1.f + __expf(-fabsf(s)));
    return sigmoid_t(f) * sp;
}

// ---------------------------------------------------------------------------
// g_ea = relu(edge_attr @ short_w + short_b)
__global__ __launch_bounds__(256) void ea_kernel(
    const float* __restrict__ attr, const float* __restrict__ sw,
    const float* __restrict__ sb, int E)
{
    __shared__ float w[NG * SL];
    __shared__ float b[SL];
    int tid = threadIdx.x;
    if (tid < NG * SL) w[tid] = sw[tid];
    if (tid < SL)      b[tid] = sb[tid];
    __syncthreads();
    int stride = gridDim.x * blockDim.x;
    for (int e = blockIdx.x * blockDim.x + tid; e < E; e += stride) {
        float a[NG];
#pragma unroll
        for (int g = 0; g < NG; g++) a[g] = __ldg(attr + (size_t)e * NG + g);
        float4* dst = (float4*)(g_ea + (size_t)e * SL);
#pragma unroll
        for (int q = 0; q < 5; q++) {
            float o[4];
#pragma unroll
            for (int j = 0; j < 4; j++) {
                float acc = b[q * 4 + j];
#pragma unroll
                for (int g = 0; g < NG; g++)
                    acc = fmaf(a[g], w[g * SL + q * 4 + j], acc);
                o[j] = fmaxf(acc, 0.f);
            }
            dst[q] = make_float4(o[0], o[1], o[2], o[3]);
        }
    }
}

// ---------------------------------------------------------------------------
// out = relu(h @ W + b)   [N,64]
__global__ __launch_bounds__(256) void lin0_kernel(
    const float* __restrict__ h, const float* __restrict__ W,
    const float* __restrict__ b, float* __restrict__ out, int N)
{
    __shared__ float sW[64 * 64];
    __shared__ float sb[64];
    int tid = threadIdx.x;
    for (int i = tid; i < 64 * 64; i += 256) sW[i] = W[i];
    if (tid < 64) sb[tid] = b[tid];
    __syncthreads();

    int c = tid & 63, rr = tid >> 6;
    for (int r0 = blockIdx.x * 4; r0 < N; r0 += gridDim.x * 4) {
        int r = r0 + rr;
        if (r < N) {
            const float* hr = h + (size_t)r * 64;
            float acc = sb[c];
#pragma unroll 16
            for (int k = 0; k < 64; k++)
                acc = fmaf(__ldg(hr + k), sW[k * 64 + c], acc);
            out[(size_t)r * 64 + c] = fmaxf(acc, 0.f);
        }
    }
}

// ---------------------------------------------------------------------------
// g_proj[n] = out[n] @ [W1f | W2f | W1s | W2s]  (+bf on Af, +bs on As)
// Layout per node (256 floats): [Af | Bf | As | Bs].
// Also zeroes g_agg and g_sums for the layer (grid-stride prologue).
__global__ __launch_bounds__(256) void node_proj_kernel(
    const float* __restrict__ out,
    const float* __restrict__ Wf, const float* __restrict__ bf,
    const float* __restrict__ Ws, const float* __restrict__ bs,
    int N)
{
    int tid = threadIdx.x;
    // zero agg + sums
    {
        float4 z = make_float4(0.f, 0.f, 0.f, 0.f);
        float4* a4 = (float4*)g_agg;
        int total = N * 16;
        int stride = gridDim.x * 256;
        for (int i = blockIdx.x * 256 + tid; i < total; i += stride) a4[i] = z;
        if (blockIdx.x == 0 && tid < 2 * NF) g_sums[tid] = 0.f;
    }

    __shared__ __align__(16) float sOut[16 * 64];
    int c = tid;
    const float* base; int col; float bias;
    if (c < 64)       { base = Wf;           col = c;        bias = __ldg(bf + c); }
    else if (c < 128) { base = Wf + 64 * 64; col = c - 64;   bias = 0.f; }
    else if (c < 192) { base = Ws;           col = c - 128;  bias = __ldg(bs + c - 128); }
    else              { base = Ws + 64 * 64; col = c - 192;  bias = 0.f; }
    float w[64];
#pragma unroll
    for (int k = 0; k < 64; k++) w[k] = __ldg(base + k * 64 + col);

    for (int r0 = blockIdx.x * 16; r0 < N; r0 += gridDim.x * 16) {
        __syncthreads();
        for (int i = tid; i < 16 * 16; i += 256) {
            int r = i >> 4, q = i & 15;
            int rr = r0 + r;
            float4 v = (rr < N) ? ((const float4*)out)[(size_t)rr * 16 + q]
                                : make_float4(0.f, 0.f, 0.f, 0.f);
            ((float4*)sOut)[r * 16 + q] = v;
        }
        __syncthreads();
        float acc[16];
#pragma unroll
        for (int r = 0; r < 16; r++) acc[r] = bias;
#pragma unroll
        for (int k4 = 0; k4 < 16; k4++) {
#pragma unroll
            for (int r = 0; r < 16; r++) {
                float4 z = ((const float4*)sOut)[r * 16 + k4];
                acc[r] = fmaf(z.x, w[k4 * 4 + 0], acc[r]);
                acc[r] = fmaf(z.y, w[k4 * 4 + 1], acc[r]);
                acc[r] = fmaf(z.z, w[k4 * 4 + 2], acc[r]);
                acc[r] = fmaf(z.w, w[k4 * 4 + 3], acc[r]);
            }
        }
#pragma unroll
        for (int r = 0; r < 16; r++) {
            int rr = r0 + r;
            if (rr < N) g_proj[(size_t)rr * 256 + c] = acc[r];
        }
    }
}

// ---------------------------------------------------------------------------
// Edge kernel (champion layout + 4-edge weight amortization):
// warp-iter handles 4 edges; lanes 0-15 do edges eA=4q+0, eB=4q+2;
// lanes 16-31 do eA=4q+1, eB=4q+3. Lane t owns channels 4t..4t+3.
// Weights (smem) loaded ONCE per k, reused for both edges -> smem wavefronts
// per edge halved vs champion. msg = sigmoid(f)*softplus(s); red.v4 scatter.
__global__ __launch_bounds__(256) void edge_kernel(
    const int* __restrict__ ei,
    const float* __restrict__ W3f, const float* __restrict__ W3s,
    int E)
{
    __shared__ __align__(16) float sF[SL * 64];
    __shared__ __align__(16) float sS[SL * 64];
    int tid = threadIdx.x;
    for (int i = tid; i < SL * 64; i += 256) { sF[i] = W3f[i]; sS[i] = W3s[i]; }
    __syncthreads();

    int lane = tid & 31;
    int t = lane & 15;
    int half = lane >> 4;
    const ulonglong2* wfp = (const ulonglong2*)sF;
    const ulonglong2* wsp = (const ulonglong2*)sS;

    long warp  = ((long)blockIdx.x * 256 + tid) >> 5;
    long nwarp = ((long)gridDim.x * 256) >> 5;
    long nquad = ((long)E + 3) >> 2;

    for (long q = warp; q < nquad; q += nwarp) {
        long eA = 4 * q + half;
        long eB = eA + 2;
        bool vA = eA < E, vB = eB < E;
        long eAc = vA ? eA : 0, eBc = vB ? eB : 0;

        int srcA = __ldg(ei + eAc), dstA = __ldg(ei + E + eAc);
        int srcB = __ldg(ei + eBc), dstB = __ldg(ei + E + eBc);

        // ea rows -> registers (5 float4 each)
        const float4* pa = (const float4*)(g_ea + eAc * SL);
        const float4* pb = (const float4*)(g_ea + eBc * SL);
        float4 A0 = __ldg(pa), A1 = __ldg(pa + 1), A2 = __ldg(pa + 2),
               A3 = __ldg(pa + 3), A4 = __ldg(pa + 4);
        float4 B0 = __ldg(pb), B1 = __ldg(pb + 1), B2 = __ldg(pb + 2),
               B3 = __ldg(pb + 3), B4 = __ldg(pb + 4);
        float eaA[20] = {A0.x, A0.y, A0.z, A0.w, A1.x, A1.y, A1.z, A1.w,
                         A2.x, A2.y, A2.z, A2.w, A3.x, A3.y, A3.z, A3.w,
                         A4.x, A4.y, A4.z, A4.w};
        float eaB[20] = {B0.x, B0.y, B0.z, B0.w, B1.x, B1.y, B1.z, B1.w,
                         B2.x, B2.y, B2.z, B2.w, B3.x, B3.y, B3.z, B3.w,
                         B4.x, B4.y, B4.z, B4.w};

        // gather node projections: segments in ulonglong2 units:
        // Af 0-15 | Bf 16-31 | As 32-47 | Bs 48-63 (each u2 = 4 floats)
        const ulonglong2* pdA = (const ulonglong2*)(g_proj + (size_t)dstA * 256);
        const ulonglong2* psA = (const ulonglong2*)(g_proj + (size_t)srcA * 256);
        const ulonglong2* pdB = (const ulonglong2*)(g_proj + (size_t)dstB * 256);
        const ulonglong2* psB = (const ulonglong2*)(g_proj + (size_t)srcB * 256);
        ulonglong2 afA = __ldg(pdA + t),      bfA = __ldg(psA + 16 + t);
        ulonglong2 asA = __ldg(pdA + 32 + t), bsA = __ldg(psA + 48 + t);
        ulonglong2 afB = __ldg(pdB + t),      bfB = __ldg(psB + 16 + t);
        ulonglong2 asB = __ldg(pdB + 32 + t), bsB = __ldg(psB + 48 + t);

        ull fA01 = add2(afA.x, bfA.x), fA23 = add2(afA.y, bfA.y);
        ull sA01 = add2(asA.x, bsA.x), sA23 = add2(asA.y, bsA.y);
        ull fB01 = add2(afB.x, bfB.x), fB23 = add2(afB.y, bfB.y);
        ull sB01 = add2(asB.x, bsB.x), sB23 = add2(asB.y, bsB.y);

#pragma unroll 4
        for (int k = 0; k < SL; k++) {
            ulonglong2 wf = wfp[k * 16 + t];
            ulonglong2 ws = wsp[k * 16 + t];
            ull aA = pack2(eaA[k]);
            ull aB = pack2(eaB[k]);
            fA01 = fma2(aA, wf.x, fA01);
            fA23 = fma2(aA, wf.y, fA23);
            sA01 = fma2(aA, ws.x, sA01);
            sA23 = fma2(aA, ws.y, sA23);
            fB01 = fma2(aB, wf.x, fB01);
            fB23 = fma2(aB, wf.y, fB23);
            sB01 = fma2(aB, ws.x, sB01);
            sB23 = fma2(aB, ws.y, sB23);
        }

        if (vA) {
            float2 F0 = unpack2(fA01), F1 = unpack2(fA23);
            float2 S0 = unpack2(sA01), S1 = unpack2(sA23);
            red_add_v4(&g_agg[(size_t)dstA * 64 + t * 4],
                       msg_fn(F0.x, S0.x), msg_fn(F0.y, S0.y),
                       msg_fn(F1.x, S1.x), msg_fn(F1.y, S1.y));
        }
        if (vB) {
            float2 F0 = unpack2(fB01), F1 = unpack2(fB23);
            float2 S0 = unpack2(sB01), S1 = unpack2(sB23);
            red_add_v4(&g_agg[(size_t)dstB * 64 + t * 4],
                       msg_fn(F0.x, S0.x), msg_fn(F0.y, S0.y),
                       msg_fn(F1.x, S1.x), msg_fn(F1.y, S1.y));
        }
    }
}

// ---------------------------------------------------------------------------
__global__ __launch_bounds__(256) void bn_stats_kernel(int N) {
    __shared__ float4 s1[256], s2[256];
    int tid = threadIdx.x;
    const float4* a4 = (const float4*)g_agg;
    int total = N * 16;
    float4 s = make_float4(0.f, 0.f, 0.f, 0.f);
    float4 q = make_float4(0.f, 0.f, 0.f, 0.f);
    int stride = gridDim.x * 256;
    for (int i = blockIdx.x * 256 + tid; i < total; i += stride) {
        float4 v = a4[i];
        s.x += v.x; s.y += v.y; s.z += v.z; s.w += v.w;
        q.x = fmaf(v.x, v.x, q.x); q.y = fmaf(v.y, v.y, q.y);
        q.z = fmaf(v.z, v.z, q.z); q.w = fmaf(v.w, v.w, q.w);
    }
    s1[tid] = s; s2[tid] = q;
    __syncthreads();
    if (tid < 16) {
        float4 S = s1[tid], Q = s2[tid];
#pragma unroll
        for (int j = 1; j < 16; j++) {
            float4 a = s1[tid + 16 * j], b = s2[tid + 16 * j];
            S.x += a.x; S.y += a.y; S.z += a.z; S.w += a.w;
            Q.x += b.x; Q.y += b.y; Q.z += b.z; Q.w += b.w;
        }
        int c0 = tid * 4;
        atomicAdd(&g_sums[c0 + 0], S.x);
        atomicAdd(&g_sums[c0 + 1], S.y);
        atomicAdd(&g_sums[c0 + 2], S.z);
        atomicAdd(&g_sums[c0 + 3], S.w);
        atomicAdd(&g_sums[64 + c0 + 0], Q.x);
        atomicAdd(&g_sums[64 + c0 + 1], Q.y);
        atomicAdd(&g_sums[64 + c0 + 2], Q.z);
        atomicAdd(&g_sums[64 + c0 + 3], Q.w);
    }
}

// ---------------------------------------------------------------------------
// out = out + relu( BN(agg) + out )
__global__ __launch_bounds__(256) void bn_apply_kernel(
    const float* __restrict__ gamma, const float* __restrict__ beta,
    float* __restrict__ out, int N, float invN)
{
    int tid = threadIdx.x;
    int c0 = (tid & 15) * 4;
    float mul[4], add[4];
#pragma unroll
    for (int j = 0; j < 4; j++) {
        float mean = g_sums[c0 + j] * invN;
        float var  = fmaf(-mean, mean, g_sums[64 + c0 + j] * invN);
        float inv  = rsqrtf(var + BN_EPS);
        float m = inv * __ldg(gamma + c0 + j);
        mul[j] = m;
        add[j] = __ldg(beta + c0 + j) - mean * m;
    }
    float4* o4 = (float4*)out;
    const float4* a4 = (const float4*)g_agg;
    int total = N * 16;
    int stride = gridDim.x * 256;
    for (int i = blockIdx.x * 256 + tid; i < total; i += stride) {
        float4 a = a4[i], o = o4[i], r;
        float bn;
        bn = fmaf(a.x, mul[0], add[0]); r.x = o.x + fmaxf(bn + o.x, 0.f);
        bn = fmaf(a.y, mul[1], add[1]); r.y = o.y + fmaxf(bn + o.y, 0.f);
        bn = fmaf(a.z, mul[2], add[2]); r.z = o.z + fmaxf(bn + o.z, 0.f);
        bn = fmaf(a.w, mul[3], add[3]); r.w = o.w + fmaxf(bn + o.w, 0.f);
        o4[i] = r;
    }
}

// ---------------------------------------------------------------------------
extern "C" void kernel_launch(void* const* d_in, const int* in_sizes, int n_in,
                              void* d_out, int out_size)
{
    const float* h      = (const float*)d_in[0];
    const int*   ei     = (const int*)  d_in[1];
    // d_in[2] = edge_weight (unused by reference)
    const float* eattr  = (const float*)d_in[3];
    const float* lin0_w = (const float*)d_in[4];
    const float* lin0_b = (const float*)d_in[5];
    const float* shw    = (const float*)d_in[6];
    const float* shb    = (const float*)d_in[7];
    const float* linf_w = (const float*)d_in[8];
    const float* linf_b = (const float*)d_in[9];
    const float* lins_w = (const float*)d_in[10];
    const float* lins_b = (const float*)d_in[11];
    const float* gamma  = (const float*)d_in[12];
    const float* beta   = (const float*)d_in[13];

    int N = in_sizes[0] / HC;
    int E = in_sizes[1] / 2;
    float* out = (float*)d_out;
    float invN = 1.f / (float)N;

    const float* Wf0 = linf_w;
    const float* Ws0 = lins_w;
    const float* Wf1 = linf_w + (size_t)ZD * NF;
    const float* Ws1 = lins_w + (size_t)ZD * NF;

    ea_kernel<<<1184, 256>>>(eattr, shw, shb, E);                          // 1
    lin0_kernel<<<592, 256>>>(h, lin0_w, lin0_b, out, N);                  // 2

    // ---- layer 0 (edge_kernel at slot 4 for ncu capture) ----
    node_proj_kernel<<<592, 256>>>(out, Wf0, linf_b, Ws0, lins_b, N);      // 3
    edge_kernel<<<1184, 256>>>(ei, Wf0 + 128 * NF, Ws0 + 128 * NF, E);     // 4
    bn_stats_kernel<<<592, 256>>>(N);                                      // 5
    bn_apply_kernel<<<592, 256>>>(gamma, beta, out, N, invN);              // 6

    // ---- layer 1 ----
    node_proj_kernel<<<592, 256>>>(out, Wf1, linf_b + NF, Ws1, lins_b + NF, N); // 7
    edge_kernel<<<1184, 256>>>(ei, Wf1 + 128 * NF, Ws1 + 128 * NF, E);          // 8
    bn_stats_kernel<<<592, 256>>>(N);                                           // 9
    bn_apply_kernel<<<592, 256>>>(gamma + NF, beta + NF, out, N, invN);         // 10
}

// round 10
// speedup vs baseline: 2.0366x; 1.1111x over previous
#include <cuda_runtime.h>
#include <math.h>

#define HC 64
#define NF 64
#define NG 5
#define SL 20
#define ZD 148
#define BN_EPS 1e-5f
#define MAX_N 50000
#define MAX_E 800000

typedef unsigned long long ull;

// Scratch (allocation-free rule: __device__ globals)
__device__ __align__(16) float g_agg[MAX_N * NF];        // per-layer aggregation
__device__ __align__(16) float g_proj[MAX_N * 4 * NF];   // [N][Af|Bf|As|Bs] fp32
__device__ __align__(16) float g_ea[(size_t)MAX_E * SL]; // relu(edge_attr@short_w)
__device__ __align__(16) float g_sums[2 * NF];           // sum / sumsq

// ---------------- packed f32x2 helpers ----------------
__device__ __forceinline__ ull fma2(ull a, ull b, ull c) {
    ull d;
    asm("fma.rn.f32x2 %0, %1, %2, %3;" : "=l"(d) : "l"(a), "l"(b), "l"(c));
    return d;
}
__device__ __forceinline__ ull add2(ull a, ull b) {
    ull d;
    asm("add.rn.f32x2 %0, %1, %2;" : "=l"(d) : "l"(a), "l"(b));
    return d;
}
__device__ __forceinline__ ull pack2(float v) {
    ull r;
    asm("mov.b64 %0, {%1, %1};" : "=l"(r) : "f"(v));
    return r;
}
__device__ __forceinline__ float2 unpack2(ull v) {
    float2 r;
    asm("mov.b64 {%0, %1}, %2;" : "=f"(r.x), "=f"(r.y) : "l"(v));
    return r;
}
// pack two fp32 into bf16x2 word (lo -> low half), round-to-nearest
__device__ __forceinline__ unsigned f2_to_bf2(float lo, float hi) {
    unsigned r;
    asm("cvt.rn.bf16x2.f32 %0, %1, %2;" : "=r"(r) : "f"(hi), "f"(lo));
    return r;
}
// expand bf16x2 word -> packed f32x2 (pure ALU: shift/and + mov)
__device__ __forceinline__ ull bf2_to_f32x2(unsigned p) {
    unsigned lo = p << 16;
    unsigned hi = p & 0xffff0000u;
    ull r;
    asm("mov.b64 %0, {%1, %2};" : "=l"(r) : "r"(lo), "r"(hi));
    return r;
}
__device__ __forceinline__ void red_add_v4(float* addr, float a, float b, float c, float d) {
    asm volatile("red.global.add.v4.f32 [%0], {%1, %2, %3, %4};"
                 :: "l"(addr), "f"(a), "f"(b), "f"(c), "f"(d) : "memory");
}
__device__ __forceinline__ float sigmoid_t(float x) {
    float t;
    asm("tanh.approx.f32 %0, %1;" : "=f"(t) : "f"(0.5f * x));
    return fmaf(0.5f, t, 0.5f);
}
__device__ __forceinline__ float msg_fn(float f, float s) {
    float sp = fmaxf(s, 0.f) + __logf(1.f + __expf(-fabsf(s)));
    return sigmoid_t(f) * sp;
}

// ---------------------------------------------------------------------------
// g_ea = relu(edge_attr @ short_w + short_b)
__global__ __launch_bounds__(256) void ea_kernel(
    const float* __restrict__ attr, const float* __restrict__ sw,
    const float* __restrict__ sb, int E)
{
    __shared__ float w[NG * SL];
    __shared__ float b[SL];
    int tid = threadIdx.x;
    if (tid < NG * SL) w[tid] = sw[tid];
    if (tid < SL)      b[tid] = sb[tid];
    __syncthreads();
    int stride = gridDim.x * blockDim.x;
    for (int e = blockIdx.x * blockDim.x + tid; e < E; e += stride) {
        float a[NG];
#pragma unroll
        for (int g = 0; g < NG; g++) a[g] = __ldg(attr + (size_t)e * NG + g);
        float4* dst = (float4*)(g_ea + (size_t)e * SL);
#pragma unroll
        for (int q = 0; q < 5; q++) {
            float o[4];
#pragma unroll
            for (int j = 0; j < 4; j++) {
                float acc = b[q * 4 + j];
#pragma unroll
                for (int g = 0; g < NG; g++)
                    acc = fmaf(a[g], w[g * SL + q * 4 + j], acc);
                o[j] = fmaxf(acc, 0.f);
            }
            dst[q] = make_float4(o[0], o[1], o[2], o[3]);
        }
    }
}

// ---------------------------------------------------------------------------
// out = relu(h @ W + b)   [N,64]
__global__ __launch_bounds__(256) void lin0_kernel(
    const float* __restrict__ h, const float* __restrict__ W,
    const float* __restrict__ b, float* __restrict__ out, int N)
{
    __shared__ float sW[64 * 64];
    __shared__ float sb[64];
    int tid = threadIdx.x;
    for (int i = tid; i < 64 * 64; i += 256) sW[i] = W[i];
    if (tid < 64) sb[tid] = b[tid];
    __syncthreads();

    int c = tid & 63, rr = tid >> 6;
    for (int r0 = blockIdx.x * 4; r0 < N; r0 += gridDim.x * 4) {
        int r = r0 + rr;
        if (r < N) {
            const float* hr = h + (size_t)r * 64;
            float acc = sb[c];
#pragma unroll 16
            for (int k = 0; k < 64; k++)
                acc = fmaf(__ldg(hr + k), sW[k * 64 + c], acc);
            out[(size_t)r * 64 + c] = fmaxf(acc, 0.f);
        }
    }
}

// ---------------------------------------------------------------------------
// g_proj[n] = out[n] @ [W1f | W2f | W1s | W2s]  (+bf on Af, +bs on As)
// Layout per node (256 floats): [Af | Bf | As | Bs].
// Also zeroes g_agg and g_sums for the layer (grid-stride prologue).
__global__ __launch_bounds__(256) void node_proj_kernel(
    const float* __restrict__ out,
    const float* __restrict__ Wf, const float* __restrict__ bf,
    const float* __restrict__ Ws, const float* __restrict__ bs,
    int N)
{
    int tid = threadIdx.x;
    // zero agg + sums
    {
        float4 z = make_float4(0.f, 0.f, 0.f, 0.f);
        float4* a4 = (float4*)g_agg;
        int total = N * 16;
        int stride = gridDim.x * 256;
        for (int i = blockIdx.x * 256 + tid; i < total; i += stride) a4[i] = z;
        if (blockIdx.x == 0 && tid < 2 * NF) g_sums[tid] = 0.f;
    }

    __shared__ __align__(16) float sOut[16 * 64];
    int c = tid;
    const float* base; int col; float bias;
    if (c < 64)       { base = Wf;           col = c;        bias = __ldg(bf + c); }
    else if (c < 128) { base = Wf + 64 * 64; col = c - 64;   bias = 0.f; }
    else if (c < 192) { base = Ws;           col = c - 128;  bias = __ldg(bs + c - 128); }
    else              { base = Ws + 64 * 64; col = c - 192;  bias = 0.f; }
    float w[64];
#pragma unroll
    for (int k = 0; k < 64; k++) w[k] = __ldg(base + k * 64 + col);

    for (int r0 = blockIdx.x * 16; r0 < N; r0 += gridDim.x * 16) {
        __syncthreads();
        for (int i = tid; i < 16 * 16; i += 256) {
            int r = i >> 4, q = i & 15;
            int rr = r0 + r;
            float4 v = (rr < N) ? ((const float4*)out)[(size_t)rr * 16 + q]
                                : make_float4(0.f, 0.f, 0.f, 0.f);
            ((float4*)sOut)[r * 16 + q] = v;
        }
        __syncthreads();
        float acc[16];
#pragma unroll
        for (int r = 0; r < 16; r++) acc[r] = bias;
#pragma unroll
        for (int k4 = 0; k4 < 16; k4++) {
#pragma unroll
            for (int r = 0; r < 16; r++) {
                float4 z = ((const float4*)sOut)[r * 16 + k4];
                acc[r] = fmaf(z.x, w[k4 * 4 + 0], acc[r]);
                acc[r] = fmaf(z.y, w[k4 * 4 + 1], acc[r]);
                acc[r] = fmaf(z.z, w[k4 * 4 + 2], acc[r]);
                acc[r] = fmaf(z.w, w[k4 * 4 + 3], acc[r]);
            }
        }
#pragma unroll
        for (int r = 0; r < 16; r++) {
            int rr = r0 + r;
            if (rr < N) g_proj[(size_t)rr * 256 + c] = acc[r];
        }
    }
}

// ---------------------------------------------------------------------------
// Edge kernel: 4 edges per warp-iter (R9 champion structure) with bf16
// interleaved weights in smem: ONE LDS.128 per k fetches {wf 4ch, ws 4ch}
// for lane t -> smem weight bytes halved vs fp32 two-array layout.
// bf16 -> f32x2 expansion is pure ALU (shift/and); fp32 accumulation.
__global__ __launch_bounds__(256) void edge_kernel(
    const int* __restrict__ ei,
    const float* __restrict__ W3f, const float* __restrict__ W3s,
    int E)
{
    // sWH[k*16 + t] = {bf2(wf[4t],wf[4t+1]), bf2(wf[4t+2],wf[4t+3]),
    //                  bf2(ws[4t],ws[4t+1]), bf2(ws[4t+2],ws[4t+3])}
    __shared__ __align__(16) uint4 sWH[SL * 16];
    int tid = threadIdx.x;
    for (int i = tid; i < SL * 16; i += 256) {
        int k = i >> 4, t4 = (i & 15) * 4;
        const float* wf = W3f + k * 64 + t4;
        const float* ws = W3s + k * 64 + t4;
        uint4 v;
        v.x = f2_to_bf2(__ldg(wf + 0), __ldg(wf + 1));
        v.y = f2_to_bf2(__ldg(wf + 2), __ldg(wf + 3));
        v.z = f2_to_bf2(__ldg(ws + 0), __ldg(ws + 1));
        v.w = f2_to_bf2(__ldg(ws + 2), __ldg(ws + 3));
        sWH[i] = v;
    }
    __syncthreads();

    int lane = tid & 31;
    int t = lane & 15;
    int half = lane >> 4;

    long warp  = ((long)blockIdx.x * 256 + tid) >> 5;
    long nwarp = ((long)gridDim.x * 256) >> 5;
    long nquad = ((long)E + 3) >> 2;

    for (long q = warp; q < nquad; q += nwarp) {
        long eA = 4 * q + half;
        long eB = eA + 2;
        bool vA = eA < E, vB = eB < E;
        long eAc = vA ? eA : 0, eBc = vB ? eB : 0;

        int srcA = __ldg(ei + eAc), dstA = __ldg(ei + E + eAc);
        int srcB = __ldg(ei + eBc), dstB = __ldg(ei + E + eBc);

        // ea rows -> registers (5 float4 each; broadcast within half)
        const float4* pa = (const float4*)(g_ea + eAc * SL);
        const float4* pb = (const float4*)(g_ea + eBc * SL);
        float4 A0 = __ldg(pa), A1 = __ldg(pa + 1), A2 = __ldg(pa + 2),
               A3 = __ldg(pa + 3), A4 = __ldg(pa + 4);
        float4 B0 = __ldg(pb), B1 = __ldg(pb + 1), B2 = __ldg(pb + 2),
               B3 = __ldg(pb + 3), B4 = __ldg(pb + 4);
        float eaA[20] = {A0.x, A0.y, A0.z, A0.w, A1.x, A1.y, A1.z, A1.w,
                         A2.x, A2.y, A2.z, A2.w, A3.x, A3.y, A3.z, A3.w,
                         A4.x, A4.y, A4.z, A4.w};
        float eaB[20] = {B0.x, B0.y, B0.z, B0.w, B1.x, B1.y, B1.z, B1.w,
                         B2.x, B2.y, B2.z, B2.w, B3.x, B3.y, B3.z, B3.w,
                         B4.x, B4.y, B4.z, B4.w};

        // gather node projections: segments in ulonglong2 units:
        // Af 0-15 | Bf 16-31 | As 32-47 | Bs 48-63
        const ulonglong2* pdA = (const ulonglong2*)(g_proj + (size_t)dstA * 256);
        const ulonglong2* psA = (const ulonglong2*)(g_proj + (size_t)srcA * 256);
        const ulonglong2* pdB = (const ulonglong2*)(g_proj + (size_t)dstB * 256);
        const ulonglong2* psB = (const ulonglong2*)(g_proj + (size_t)srcB * 256);
        ulonglong2 afA = __ldg(pdA + t),      bfA = __ldg(psA + 16 + t);
        ulonglong2 asA = __ldg(pdA + 32 + t), bsA = __ldg(psA + 48 + t);
        ulonglong2 afB = __ldg(pdB + t),      bfB = __ldg(psB + 16 + t);
        ulonglong2 asB = __ldg(pdB + 32 + t), bsB = __ldg(psB + 48 + t);

        ull fA01 = add2(afA.x, bfA.x), fA23 = add2(afA.y, bfA.y);
        ull sA01 = add2(asA.x, bsA.x), sA23 = add2(asA.y, bsA.y);
        ull fB01 = add2(afB.x, bfB.x), fB23 = add2(afB.y, bfB.y);
        ull sB01 = add2(asB.x, bsB.x), sB23 = add2(asB.y, bsB.y);

#pragma unroll 4
        for (int k = 0; k < SL; k++) {
            uint4 wp = sWH[k * 16 + t];      // one LDS.128: wf+ws, 4 channels
            ull wf01 = bf2_to_f32x2(wp.x);
            ull wf23 = bf2_to_f32x2(wp.y);
            ull ws01 = bf2_to_f32x2(wp.z);
            ull ws23 = bf2_to_f32x2(wp.w);
            ull aA = pack2(eaA[k]);
            ull aB = pack2(eaB[k]);
            fA01 = fma2(aA, wf01, fA01);
            fA23 = fma2(aA, wf23, fA23);
            sA01 = fma2(aA, ws01, sA01);
            sA23 = fma2(aA, ws23, sA23);
            fB01 = fma2(aB, wf01, fB01);
            fB23 = fma2(aB, wf23, fB23);
            sB01 = fma2(aB, ws01, sB01);
            sB23 = fma2(aB, ws23, sB23);
        }

        if (vA) {
            float2 F0 = unpack2(fA01), F1 = unpack2(fA23);
            float2 S0 = unpack2(sA01), S1 = unpack2(sA23);
            red_add_v4(&g_agg[(size_t)dstA * 64 + t * 4],
                       msg_fn(F0.x, S0.x), msg_fn(F0.y, S0.y),
                       msg_fn(F1.x, S1.x), msg_fn(F1.y, S1.y));
        }
        if (vB) {
            float2 F0 = unpack2(fB01), F1 = unpack2(fB23);
            float2 S0 = unpack2(sB01), S1 = unpack2(sB23);
            red_add_v4(&g_agg[(size_t)dstB * 64 + t * 4],
                       msg_fn(F0.x, S0.x), msg_fn(F0.y, S0.y),
                       msg_fn(F1.x, S1.x), msg_fn(F1.y, S1.y));
        }
    }
}

// ---------------------------------------------------------------------------
__global__ __launch_bounds__(256) void bn_stats_kernel(int N) {
    __shared__ float4 s1[256], s2[256];
    int tid = threadIdx.x;
    const float4* a4 = (const float4*)g_agg;
    int total = N * 16;
    float4 s = make_float4(0.f, 0.f, 0.f, 0.f);
    float4 q = make_float4(0.f, 0.f, 0.f, 0.f);
    int stride = gridDim.x * 256;
    for (int i = blockIdx.x * 256 + tid; i < total; i += stride) {
        float4 v = a4[i];
        s.x += v.x; s.y += v.y; s.z += v.z; s.w += v.w;
        q.x = fmaf(v.x, v.x, q.x); q.y = fmaf(v.y, v.y, q.y);
        q.z = fmaf(v.z, v.z, q.z); q.w = fmaf(v.w, v.w, q.w);
    }
    s1[tid] = s; s2[tid] = q;
    __syncthreads();
    if (tid < 16) {
        float4 S = s1[tid], Q = s2[tid];
#pragma unroll
        for (int j = 1; j < 16; j++) {
            float4 a = s1[tid + 16 * j], b = s2[tid + 16 * j];
            S.x += a.x; S.y += a.y; S.z += a.z; S.w += a.w;
            Q.x += b.x; Q.y += b.y; Q.z += b.z; Q.w += b.w;
        }
        int c0 = tid * 4;
        atomicAdd(&g_sums[c0 + 0], S.x);
        atomicAdd(&g_sums[c0 + 1], S.y);
        atomicAdd(&g_sums[c0 + 2], S.z);
        atomicAdd(&g_sums[c0 + 3], S.w);
        atomicAdd(&g_sums[64 + c0 + 0], Q.x);
        atomicAdd(&g_sums[64 + c0 + 1], Q.y);
        atomicAdd(&g_sums[64 + c0 + 2], Q.z);
        atomicAdd(&g_sums[64 + c0 + 3], Q.w);
    }
}

// ---------------------------------------------------------------------------
// out = out + relu( BN(agg) + out )
__global__ __launch_bounds__(256) void bn_apply_kernel(
    const float* __restrict__ gamma, const float* __restrict__ beta,
    float* __restrict__ out, int N, float invN)
{
    int tid = threadIdx.x;
    int c0 = (tid & 15) * 4;
    float mul[4], add[4];
#pragma unroll
    for (int j = 0; j < 4; j++) {
        float mean = g_sums[c0 + j] * invN;
        float var  = fmaf(-mean, mean, g_sums[64 + c0 + j] * invN);
        float inv  = rsqrtf(var + BN_EPS);
        float m = inv * __ldg(gamma + c0 + j);
        mul[j] = m;
        add[j] = __ldg(beta + c0 + j) - mean * m;
    }
    float4* o4 = (float4*)out;
    const float4* a4 = (const float4*)g_agg;
    int total = N * 16;
    int stride = gridDim.x * 256;
    for (int i = blockIdx.x * 256 + tid; i < total; i += stride) {
        float4 a = a4[i], o = o4[i], r;
        float bn;
        bn = fmaf(a.x, mul[0], add[0]); r.x = o.x + fmaxf(bn + o.x, 0.f);
        bn = fmaf(a.y, mul[1], add[1]); r.y = o.y + fmaxf(bn + o.y, 0.f);
        bn = fmaf(a.z, mul[2], add[2]); r.z = o.z + fmaxf(bn + o.z, 0.f);
        bn = fmaf(a.w, mul[3], add[3]); r.w = o.w + fmaxf(bn + o.w, 0.f);
        o4[i] = r;
    }
}

// ---------------------------------------------------------------------------
extern "C" void kernel_launch(void* const* d_in, const int* in_sizes, int n_in,
                              void* d_out, int out_size)
{
    const float* h      = (const float*)d_in[0];
    const int*   ei     = (const int*)  d_in[1];
    // d_in[2] = edge_weight (unused by reference)
    const float* eattr  = (const float*)d_in[3];
    const float* lin0_w = (const float*)d_in[4];
    const float* lin0_b = (const float*)d_in[5];
    const float* shw    = (const float*)d_in[6];
    const float* shb    = (const float*)d_in[7];
    const float* linf_w = (const float*)d_in[8];
    const float* linf_b = (const float*)d_in[9];
    const float* lins_w = (const float*)d_in[10];
    const float* lins_b = (const float*)d_in[11];
    const float* gamma  = (const float*)d_in[12];
    const float* beta   = (const float*)d_in[13];

    int N = in_sizes[0] / HC;
    int E = in_sizes[1] / 2;
    float* out = (float*)d_out;
    float invN = 1.f / (float)N;

    const float* Wf0 = linf_w;
    const float* Ws0 = lins_w;
    const float* Wf1 = linf_w + (size_t)ZD * NF;
    const float* Ws1 = lins_w + (size_t)ZD * NF;

    ea_kernel<<<1184, 256>>>(eattr, shw, shb, E);                          // 1
    lin0_kernel<<<592, 256>>>(h, lin0_w, lin0_b, out, N);                  // 2

    // ---- layer 0 (edge_kernel at slot 4 for ncu capture) ----
    node_proj_kernel<<<592, 256>>>(out, Wf0, linf_b, Ws0, lins_b, N);      // 3
    edge_kernel<<<1184, 256>>>(ei, Wf0 + 128 * NF, Ws0 + 128 * NF, E);     // 4
    bn_stats_kernel<<<592, 256>>>(N);                                      // 5
    bn_apply_kernel<<<592, 256>>>(gamma, beta, out, N, invN);              // 6

    // ---- layer 1 ----
    node_proj_kernel<<<592, 256>>>(out, Wf1, linf_b + NF, Ws1, lins_b + NF, N); // 7
    edge_kernel<<<1184, 256>>>(ei, Wf1 + 128 * NF, Ws1 + 128 * NF, E);          // 8
    bn_stats_kernel<<<592, 256>>>(N);                                           // 9
    bn_apply_kernel<<<592, 256>>>(gamma + NF, beta + NF, out, N, invN);         // 10
}